// round 3
// baseline (speedup 1.0000x reference)
#include <cuda_runtime.h>
#include <cstdint>

// ---------------------------------------------------------------------------
// GCN 2-layer: out = gcnconv2( relu( gcnconv1(x) ) )
// R3: f32x2 packed-FMA GEMM (FFMA2) + fused self-loop/bias epilogue.
// ---------------------------------------------------------------------------

#define N_MAX 100000
#define E_MAX 1600000
#define F_DIM 128

__device__ float g_A[(size_t)N_MAX * F_DIM];   // gemm output (lin)
__device__ float g_B[(size_t)N_MAX * F_DIM];   // aggregated layer-1 output
__device__ float g_deg[N_MAX];
__device__ float g_dinv[N_MAX];
__device__ int   g_src[E_MAX];
__device__ int   g_dst[E_MAX];
__device__ float g_norm[E_MAX];
__device__ int   g_is64;

// --- int64 vs int32 edge_index detection (odd 32-bit words all-zero => i64) --
__global__ void k_detect(const unsigned* __restrict__ w) {
    __shared__ unsigned s;
    if (threadIdx.x == 0) s = 0u;
    __syncthreads();
    unsigned v = 0;
    for (int i = threadIdx.x; i < 4096; i += blockDim.x) v |= w[2 * i + 1];
    if (v) atomicOr(&s, 1u);
    __syncthreads();
    if (threadIdx.x == 0) g_is64 = (s == 0u) ? 1 : 0;
}

__global__ void k_initdeg(int N) {
    int i = blockIdx.x * blockDim.x + threadIdx.x;
    if (i < N) g_deg[i] = 1.0f;   // self-loop
}

__global__ void k_deg(const void* __restrict__ ei, const float* __restrict__ w, int E) {
    int e = blockIdx.x * blockDim.x + threadIdx.x;
    if (e >= E) return;
    int s, d;
    if (g_is64) {
        const long long* p = (const long long*)ei;
        s = (int)p[e];
        d = (int)p[(size_t)E + e];
    } else {
        const int* p = (const int*)ei;
        s = p[e];
        d = p[(size_t)E + e];
    }
    g_src[e] = s;
    g_dst[e] = d;
    atomicAdd(&g_deg[d], w[e]);
}

__global__ void k_dinv(int N) {
    int i = blockIdx.x * blockDim.x + threadIdx.x;
    if (i >= N) return;
    float dg = g_deg[i];
    g_dinv[i] = (dg > 0.0f) ? rsqrtf(dg) : 0.0f;
}

__global__ void k_norm(const float* __restrict__ w, int E) {
    int e = blockIdx.x * blockDim.x + threadIdx.x;
    if (e >= E) return;
    g_norm[e] = g_dinv[g_src[e]] * w[e] * g_dinv[g_dst[e]];
}

// ---------------------------------------------------------------------------
// f32x2 helpers
// ---------------------------------------------------------------------------
__device__ __forceinline__ unsigned long long pack_dup(float a) {
    unsigned long long r;
    asm("mov.b64 %0, {%1, %1};" : "=l"(r) : "f"(a));
    return r;
}
__device__ __forceinline__ void ffma2(unsigned long long& acc,
                                      unsigned long long a,
                                      unsigned long long b) {
    asm("fma.rn.f32x2 %0, %1, %2, %0;" : "+l"(acc) : "l"(a), "l"(b));
}
__device__ __forceinline__ void unpack2(unsigned long long v, float& lo, float& hi) {
    asm("mov.b64 {%0, %1}, %2;" : "=f"(lo), "=f"(hi) : "l"(v));
}

// ---------------------------------------------------------------------------
// SGEMM (FFMA2): C[M,128] = act(X[M,K]) @ W[K,128]
// BM=64, BN=128, BK=16; 256 threads; 4x8 outputs per thread (4x4 f32x2 accs).
// Fused epilogue: lin = C;  agg = dinv[r]^2 * C + bias   (self-loop + bias)
// ---------------------------------------------------------------------------
template <bool RELU>
__global__ __launch_bounds__(256) void k_sgemm128(
    const float* __restrict__ X, const float* __restrict__ W,
    const float* __restrict__ bias,
    float* __restrict__ lin, float* __restrict__ agg,
    int M, int K)
{
    __shared__ float Xs[16][64];
    __shared__ float Ws[16][128];

    const int tid = threadIdx.x;
    const int tr = tid >> 4;        // 0..15
    const int tc = tid & 15;        // 0..15
    const int rowBase = blockIdx.x * 64;

    const int ldr = tid >> 2;           // 0..63
    const int ldk = (tid & 3) * 4;      // 0,4,8,12
    const int wrow = tid >> 4;          // 0..15
    const int wcol = (tid & 15) * 8;    // 0..120

    unsigned long long acc2[4][4];
#pragma unroll
    for (int i = 0; i < 4; i++)
#pragma unroll
        for (int j = 0; j < 4; j++) acc2[i][j] = 0ull;

    for (int k0 = 0; k0 < K; k0 += 16) {
        float4 xv = make_float4(0.f, 0.f, 0.f, 0.f);
        int gr = rowBase + ldr;
        if (gr < M) xv = *(const float4*)(X + (size_t)gr * K + k0 + ldk);
        if (RELU) {
            xv.x = fmaxf(xv.x, 0.f); xv.y = fmaxf(xv.y, 0.f);
            xv.z = fmaxf(xv.z, 0.f); xv.w = fmaxf(xv.w, 0.f);
        }
        Xs[ldk + 0][ldr] = xv.x;
        Xs[ldk + 1][ldr] = xv.y;
        Xs[ldk + 2][ldr] = xv.z;
        Xs[ldk + 3][ldr] = xv.w;

        float4 w0 = *(const float4*)(W + (size_t)(k0 + wrow) * 128 + wcol);
        float4 w1 = *(const float4*)(W + (size_t)(k0 + wrow) * 128 + wcol + 4);
        *(float4*)&Ws[wrow][wcol]     = w0;
        *(float4*)&Ws[wrow][wcol + 4] = w1;

        __syncthreads();

#pragma unroll
        for (int kk = 0; kk < 16; kk++) {
            float4 av = *(const float4*)&Xs[kk][tr * 4];
            ulonglong2 b01 = *(const ulonglong2*)&Ws[kk][tc * 8];       // pairs (b0,b1),(b2,b3)
            ulonglong2 b23 = *(const ulonglong2*)&Ws[kk][tc * 8 + 4];   // pairs (b4,b5),(b6,b7)
            unsigned long long bb0 = b01.x, bb1 = b01.y, bb2 = b23.x, bb3 = b23.y;

            unsigned long long a0 = pack_dup(av.x);
            unsigned long long a1 = pack_dup(av.y);
            unsigned long long a2 = pack_dup(av.z);
            unsigned long long a3 = pack_dup(av.w);

            ffma2(acc2[0][0], a0, bb0); ffma2(acc2[0][1], a0, bb1);
            ffma2(acc2[0][2], a0, bb2); ffma2(acc2[0][3], a0, bb3);
            ffma2(acc2[1][0], a1, bb0); ffma2(acc2[1][1], a1, bb1);
            ffma2(acc2[1][2], a1, bb2); ffma2(acc2[1][3], a1, bb3);
            ffma2(acc2[2][0], a2, bb0); ffma2(acc2[2][1], a2, bb1);
            ffma2(acc2[2][2], a2, bb2); ffma2(acc2[2][3], a2, bb3);
            ffma2(acc2[3][0], a3, bb0); ffma2(acc2[3][1], a3, bb1);
            ffma2(acc2[3][2], a3, bb2); ffma2(acc2[3][3], a3, bb3);
        }
        __syncthreads();
    }

    // bias for this thread's 8 columns
    float4 bb_lo = *(const float4*)(bias + tc * 8);
    float4 bb_hi = *(const float4*)(bias + tc * 8 + 4);
    float bcol[8] = {bb_lo.x, bb_lo.y, bb_lo.z, bb_lo.w,
                     bb_hi.x, bb_hi.y, bb_hi.z, bb_hi.w};

#pragma unroll
    for (int i = 0; i < 4; i++) {
        int r = rowBase + tr * 4 + i;
        if (r >= M) continue;
        float c[8];
        unpack2(acc2[i][0], c[0], c[1]);
        unpack2(acc2[i][1], c[2], c[3]);
        unpack2(acc2[i][2], c[4], c[5]);
        unpack2(acc2[i][3], c[6], c[7]);

        float di = g_dinv[r];
        float s = di * di;

        float4 l0 = make_float4(c[0], c[1], c[2], c[3]);
        float4 l1 = make_float4(c[4], c[5], c[6], c[7]);
        *(float4*)(lin + (size_t)r * 128 + tc * 8)     = l0;
        *(float4*)(lin + (size_t)r * 128 + tc * 8 + 4) = l1;

        float4 o0 = make_float4(fmaf(c[0], s, bcol[0]), fmaf(c[1], s, bcol[1]),
                                fmaf(c[2], s, bcol[2]), fmaf(c[3], s, bcol[3]));
        float4 o1 = make_float4(fmaf(c[4], s, bcol[4]), fmaf(c[5], s, bcol[5]),
                                fmaf(c[6], s, bcol[6]), fmaf(c[7], s, bcol[7]));
        *(float4*)(agg + (size_t)r * 128 + tc * 8)     = o0;
        *(float4*)(agg + (size_t)r * 128 + tc * 8 + 4) = o1;
    }
}

// ---------------------------------------------------------------------------
// Edge scatter: one warp per edge; lane l handles 16B slice of the 512B row.
// ---------------------------------------------------------------------------
__global__ __launch_bounds__(256) void k_scatter(
    const float* __restrict__ lin, float* __restrict__ out, int E)
{
    int gt = blockIdx.x * blockDim.x + threadIdx.x;
    int e = gt >> 5;
    if (e >= E) return;
    int lane = gt & 31;
    int s = g_src[e];
    int d = g_dst[e];
    float nv = g_norm[e];
    float4 v = ((const float4*)lin)[(size_t)s * 32 + lane];
    v.x *= nv; v.y *= nv; v.z *= nv; v.w *= nv;
    float* addr = out + (size_t)d * 128 + lane * 4;
    asm volatile("red.global.add.v4.f32 [%0], {%1, %2, %3, %4};"
                 :: "l"(addr), "f"(v.x), "f"(v.y), "f"(v.z), "f"(v.w)
                 : "memory");
}

// ---------------------------------------------------------------------------

static inline int cdiv(long long a, long long b) { return (int)((a + b - 1) / b); }

extern "C" void kernel_launch(void* const* d_in, const int* in_sizes, int n_in,
                              void* d_out, int out_size)
{
    const float* x   = (const float*)d_in[0];
    const void*  ei  = d_in[1];
    const float* ew  = (const float*)d_in[2];
    const float* W1  = (const float*)d_in[3];
    const float* b1  = (const float*)d_in[4];
    const float* W2  = (const float*)d_in[5];
    const float* b2  = (const float*)d_in[6];
    float* out = (float*)d_out;

    const int HID = in_sizes[4];                 // 128
    const int K1  = in_sizes[3] / HID;           // 256
    const int N   = in_sizes[0] / K1;            // 100000
    const int E   = in_sizes[2];                 // 1600000

    float* A; float* B;
    cudaGetSymbolAddress((void**)&A, g_A);
    cudaGetSymbolAddress((void**)&B, g_B);

    const int T = 256;

    // --- graph normalization ---
    k_detect<<<1, T>>>((const unsigned*)ei);
    k_initdeg<<<cdiv(N, T), T>>>(N);
    k_deg<<<cdiv(E, T), T>>>(ei, ew, E);
    k_dinv<<<cdiv(N, T), T>>>(N);
    k_norm<<<cdiv(E, T), T>>>(ew, E);

    // --- layer 1: A = x@W1 (lin), B = dinv^2*A + b1; B += scatter ---
    k_sgemm128<false><<<cdiv(N, 64), T>>>(x, W1, b1, A, B, N, K1);
    k_scatter<<<cdiv((long long)E * 32, T), T>>>(A, B, E);

    // --- layer 2: A = relu(B)@W2 (lin), out = dinv^2*A + b2; out += scatter ---
    k_sgemm128<true><<<cdiv(N, 64), T>>>(B, W2, b2, A, out, N, HID);
    k_scatter<<<cdiv((long long)E * 32, T), T>>>(A, out, E);
}

// round 4
// speedup vs baseline: 1.5080x; 1.5080x over previous
#include <cuda_runtime.h>
#include <cstdint>

// ---------------------------------------------------------------------------
// GCN 2-layer. R4: CSR-gather aggregation (no atomics on features),
// fused self-loop+bias in gather; proven R2 fp32 GEMM (lin only).
// ---------------------------------------------------------------------------

#define N_MAX 100000
#define E_MAX 1600000
#define F_DIM 128
#define NB_MAX 512          // max scan blocks (N_MAX/256 = 391)

__device__ float g_A[(size_t)N_MAX * F_DIM];   // gemm output (lin)
__device__ float g_B[(size_t)N_MAX * F_DIM];   // aggregated layer-1 output
__device__ float g_deg[N_MAX];
__device__ float g_dinv[N_MAX];
__device__ int   g_cnt[N_MAX];                 // in-degree (excl self)
__device__ int   g_off[N_MAX];                 // block-local exclusive scan
__device__ int   g_rowptr[N_MAX];              // CSR row start
__device__ int   g_cursor[N_MAX];              // fill cursors
__device__ int   g_bsum[NB_MAX];
__device__ int   g_bscan[NB_MAX];
__device__ int   g_csrc[E_MAX];                // CSR src per slot
__device__ float g_cnorm[E_MAX];               // CSR norm per slot
__device__ int   g_is64;

// --- int64 vs int32 edge_index detection ---
__global__ void k_detect(const unsigned* __restrict__ w) {
    __shared__ unsigned s;
    if (threadIdx.x == 0) s = 0u;
    __syncthreads();
    unsigned v = 0;
    for (int i = threadIdx.x; i < 4096; i += blockDim.x) v |= w[2 * i + 1];
    if (v) atomicOr(&s, 1u);
    __syncthreads();
    if (threadIdx.x == 0) g_is64 = (s == 0u) ? 1 : 0;
}

__device__ __forceinline__ void edge_decode(const void* ei, int E, int e,
                                            int& s, int& d) {
    if (g_is64) {
        const long long* p = (const long long*)ei;
        s = (int)p[e];
        d = (int)p[(size_t)E + e];
    } else {
        const int* p = (const int*)ei;
        s = p[e];
        d = p[(size_t)E + e];
    }
}

__global__ void k_initdeg(int N) {
    int i = blockIdx.x * blockDim.x + threadIdx.x;
    if (i < N) { g_deg[i] = 1.0f; g_cnt[i] = 0; }
}

__global__ void k_deg(const void* __restrict__ ei, const float* __restrict__ w, int E) {
    int e = blockIdx.x * blockDim.x + threadIdx.x;
    if (e >= E) return;
    int s, d;
    edge_decode(ei, E, e, s, d);
    atomicAdd(&g_deg[d], w[e]);
    atomicAdd(&g_cnt[d], 1);
}

__global__ void k_dinv(int N) {
    int i = blockIdx.x * blockDim.x + threadIdx.x;
    if (i >= N) return;
    float dg = g_deg[i];
    g_dinv[i] = (dg > 0.0f) ? rsqrtf(dg) : 0.0f;
}

// --- 2-level exclusive scan of g_cnt -> g_rowptr ---
__global__ void k_scan1(int N) {
    __shared__ int sh[256];
    int t = threadIdx.x;
    int i = blockIdx.x * 256 + t;
    int v = (i < N) ? g_cnt[i] : 0;
    sh[t] = v;
    __syncthreads();
#pragma unroll
    for (int off = 1; off < 256; off <<= 1) {
        int a = (t >= off) ? sh[t - off] : 0;
        __syncthreads();
        sh[t] += a;
        __syncthreads();
    }
    if (i < N) g_off[i] = sh[t] - v;       // exclusive
    if (t == 255) g_bsum[blockIdx.x] = sh[255];
}

__global__ void k_scan2(int NB) {
    __shared__ int sh[NB_MAX];
    int t = threadIdx.x;
    int v = (t < NB) ? g_bsum[t] : 0;
    sh[t] = v;
    __syncthreads();
#pragma unroll
    for (int off = 1; off < NB_MAX; off <<= 1) {
        int a = (t >= off) ? sh[t - off] : 0;
        __syncthreads();
        sh[t] += a;
        __syncthreads();
    }
    if (t < NB) g_bscan[t] = sh[t] - v;    // exclusive
}

__global__ void k_scan3(int N) {
    int i = blockIdx.x * blockDim.x + threadIdx.x;
    if (i >= N) return;
    int rp = g_off[i] + g_bscan[i >> 8];
    g_rowptr[i] = rp;
    g_cursor[i] = rp;
}

// --- CSR fill: slot = cursor[dst]++; store src + norm ---
__global__ void k_fill(const void* __restrict__ ei, const float* __restrict__ w, int E) {
    int e = blockIdx.x * blockDim.x + threadIdx.x;
    if (e >= E) return;
    int s, d;
    edge_decode(ei, E, e, s, d);
    int pos = atomicAdd(&g_cursor[d], 1);
    g_csrc[pos] = s;
    g_cnorm[pos] = g_dinv[s] * w[e] * g_dinv[d];
}

// ---------------------------------------------------------------------------
// SGEMM (R2-proven): C[M,128] = act(X[M,K]) @ W[K,128]
// BM=64, BN=128, BK=16; 256 threads; 4x8 per thread. Writes lin only.
// ---------------------------------------------------------------------------
template <bool RELU>
__global__ __launch_bounds__(256) void k_sgemm128(
    const float* __restrict__ X, const float* __restrict__ W,
    float* __restrict__ C, int M, int K)
{
    __shared__ float Xs[16][64];
    __shared__ float Ws[16][128];

    const int tid = threadIdx.x;
    const int tr = tid >> 4;
    const int tc = tid & 15;
    const int rowBase = blockIdx.x * 64;

    const int ldr = tid >> 2;
    const int ldk = (tid & 3) * 4;
    const int wrow = tid >> 4;
    const int wcol = (tid & 15) * 8;

    float acc[4][8];
#pragma unroll
    for (int i = 0; i < 4; i++)
#pragma unroll
        for (int j = 0; j < 8; j++) acc[i][j] = 0.0f;

    for (int k0 = 0; k0 < K; k0 += 16) {
        float4 xv = make_float4(0.f, 0.f, 0.f, 0.f);
        int gr = rowBase + ldr;
        if (gr < M) xv = *(const float4*)(X + (size_t)gr * K + k0 + ldk);
        if (RELU) {
            xv.x = fmaxf(xv.x, 0.f); xv.y = fmaxf(xv.y, 0.f);
            xv.z = fmaxf(xv.z, 0.f); xv.w = fmaxf(xv.w, 0.f);
        }
        Xs[ldk + 0][ldr] = xv.x;
        Xs[ldk + 1][ldr] = xv.y;
        Xs[ldk + 2][ldr] = xv.z;
        Xs[ldk + 3][ldr] = xv.w;

        float4 w0 = *(const float4*)(W + (size_t)(k0 + wrow) * 128 + wcol);
        float4 w1 = *(const float4*)(W + (size_t)(k0 + wrow) * 128 + wcol + 4);
        *(float4*)&Ws[wrow][wcol]     = w0;
        *(float4*)&Ws[wrow][wcol + 4] = w1;

        __syncthreads();

#pragma unroll
        for (int kk = 0; kk < 16; kk++) {
            float a[4], b[8];
            *(float4*)a       = *(const float4*)&Xs[kk][tr * 4];
            *(float4*)b       = *(const float4*)&Ws[kk][tc * 8];
            *(float4*)(b + 4) = *(const float4*)&Ws[kk][tc * 8 + 4];
#pragma unroll
            for (int i = 0; i < 4; i++)
#pragma unroll
                for (int j = 0; j < 8; j++)
                    acc[i][j] = fmaf(a[i], b[j], acc[i][j]);
        }
        __syncthreads();
    }

#pragma unroll
    for (int i = 0; i < 4; i++) {
        int r = rowBase + tr * 4 + i;
        if (r < M) {
            float4 o0 = make_float4(acc[i][0], acc[i][1], acc[i][2], acc[i][3]);
            float4 o1 = make_float4(acc[i][4], acc[i][5], acc[i][6], acc[i][7]);
            *(float4*)(C + (size_t)r * 128 + tc * 8)     = o0;
            *(float4*)(C + (size_t)r * 128 + tc * 8 + 4) = o1;
        }
    }
}

// ---------------------------------------------------------------------------
// CSR gather: one warp per dst node; lane l owns float4 slice l (128 floats /
// 32 lanes). out[d] = dinv[d]^2*lin[d] + bias + sum_e norm[e]*lin[src[e]].
// ---------------------------------------------------------------------------
__global__ __launch_bounds__(256) void k_gather(
    const float* __restrict__ lin, const float* __restrict__ bias,
    float* __restrict__ out, int N)
{
    int warp = (blockIdx.x * blockDim.x + threadIdx.x) >> 5;
    if (warp >= N) return;
    int lane = threadIdx.x & 31;
    int d = warp;

    float di = g_dinv[d];
    float s = di * di;
    float4 b4 = ((const float4*)bias)[lane];
    float4 v = ((const float4*)lin)[(size_t)d * 32 + lane];
    float4 acc = make_float4(fmaf(v.x, s, b4.x), fmaf(v.y, s, b4.y),
                             fmaf(v.z, s, b4.z), fmaf(v.w, s, b4.w));

    int beg = g_rowptr[d];
    int end = beg + g_cnt[d];
    int e = beg;
    // unroll by 2 for MLP
    for (; e + 1 < end; e += 2) {
        int s0 = g_csrc[e];     float n0 = g_cnorm[e];
        int s1 = g_csrc[e + 1]; float n1 = g_cnorm[e + 1];
        float4 u0 = ((const float4*)lin)[(size_t)s0 * 32 + lane];
        float4 u1 = ((const float4*)lin)[(size_t)s1 * 32 + lane];
        acc.x = fmaf(u0.x, n0, acc.x); acc.y = fmaf(u0.y, n0, acc.y);
        acc.z = fmaf(u0.z, n0, acc.z); acc.w = fmaf(u0.w, n0, acc.w);
        acc.x = fmaf(u1.x, n1, acc.x); acc.y = fmaf(u1.y, n1, acc.y);
        acc.z = fmaf(u1.z, n1, acc.z); acc.w = fmaf(u1.w, n1, acc.w);
    }
    if (e < end) {
        int s0 = g_csrc[e]; float n0 = g_cnorm[e];
        float4 u0 = ((const float4*)lin)[(size_t)s0 * 32 + lane];
        acc.x = fmaf(u0.x, n0, acc.x); acc.y = fmaf(u0.y, n0, acc.y);
        acc.z = fmaf(u0.z, n0, acc.z); acc.w = fmaf(u0.w, n0, acc.w);
    }
    ((float4*)out)[(size_t)d * 32 + lane] = acc;
}

// ---------------------------------------------------------------------------

static inline int cdiv(long long a, long long b) { return (int)((a + b - 1) / b); }

extern "C" void kernel_launch(void* const* d_in, const int* in_sizes, int n_in,
                              void* d_out, int out_size)
{
    const float* x   = (const float*)d_in[0];
    const void*  ei  = d_in[1];
    const float* ew  = (const float*)d_in[2];
    const float* W1  = (const float*)d_in[3];
    const float* b1  = (const float*)d_in[4];
    const float* W2  = (const float*)d_in[5];
    const float* b2  = (const float*)d_in[6];
    float* out = (float*)d_out;

    const int HID = in_sizes[4];                 // 128
    const int K1  = in_sizes[3] / HID;           // 256
    const int N   = in_sizes[0] / K1;            // 100000
    const int E   = in_sizes[2];                 // 1600000

    float* A; float* B;
    cudaGetSymbolAddress((void**)&A, g_A);
    cudaGetSymbolAddress((void**)&B, g_B);

    const int T = 256;
    const int NB = cdiv(N, 256);

    // --- graph normalization + CSR build ---
    k_detect<<<1, T>>>((const unsigned*)ei);
    k_initdeg<<<cdiv(N, T), T>>>(N);
    k_deg<<<cdiv(E, T), T>>>(ei, ew, E);
    k_dinv<<<cdiv(N, T), T>>>(N);
    k_scan1<<<NB, 256>>>(N);
    k_scan2<<<1, NB_MAX>>>(NB);
    k_scan3<<<cdiv(N, T), T>>>(N);
    k_fill<<<cdiv(E, T), T>>>(ei, ew, E);

    // --- layer 1 ---
    k_sgemm128<false><<<cdiv(N, 64), T>>>(x, W1, A, N, K1);
    k_gather<<<cdiv((long long)N * 32, T), T>>>(A, b1, B, N);

    // --- layer 2 ---
    k_sgemm128<true><<<cdiv(N, 64), T>>>(B, W2, A, N, HID);
    k_gather<<<cdiv((long long)N * 32, T), T>>>(A, b2, out, N);
}

// round 5
// speedup vs baseline: 2.4957x; 1.6550x over previous
#include <cuda_runtime.h>
#include <cstdint>

// ---------------------------------------------------------------------------
// GCN 2-layer. R5: tf32 tensor-core GEMM (mma.sync m16n8k8) + CSR gather.
// ---------------------------------------------------------------------------

#define N_MAX 100000
#define E_MAX 1600000
#define F_DIM 128
#define NB_MAX 512

__device__ float g_A[(size_t)N_MAX * F_DIM];
__device__ float g_B[(size_t)N_MAX * F_DIM];
__device__ float g_deg[N_MAX];
__device__ float g_dinv[N_MAX];
__device__ int   g_cnt[N_MAX];
__device__ int   g_off[N_MAX];
__device__ int   g_rowptr[N_MAX];
__device__ int   g_cursor[N_MAX];
__device__ int   g_bsum[NB_MAX];
__device__ int   g_bscan[NB_MAX];
__device__ int   g_csrc[E_MAX];
__device__ float g_cnorm[E_MAX];
__device__ int   g_is64;

// --- int64 vs int32 edge_index detection ---
__global__ void k_detect(const unsigned* __restrict__ w) {
    __shared__ unsigned s;
    if (threadIdx.x == 0) s = 0u;
    __syncthreads();
    unsigned v = 0;
    for (int i = threadIdx.x; i < 4096; i += blockDim.x) v |= w[2 * i + 1];
    if (v) atomicOr(&s, 1u);
    __syncthreads();
    if (threadIdx.x == 0) g_is64 = (s == 0u) ? 1 : 0;
}

__device__ __forceinline__ void edge_decode(const void* ei, int E, int e,
                                            int& s, int& d) {
    if (g_is64) {
        const long long* p = (const long long*)ei;
        s = (int)p[e];
        d = (int)p[(size_t)E + e];
    } else {
        const int* p = (const int*)ei;
        s = p[e];
        d = p[(size_t)E + e];
    }
}

__global__ void k_initdeg(int N) {
    int i = blockIdx.x * blockDim.x + threadIdx.x;
    if (i < N) { g_deg[i] = 1.0f; g_cnt[i] = 0; }
}

__global__ void k_deg(const void* __restrict__ ei, const float* __restrict__ w, int E) {
    int e = blockIdx.x * blockDim.x + threadIdx.x;
    if (e >= E) return;
    int s, d;
    edge_decode(ei, E, e, s, d);
    atomicAdd(&g_deg[d], w[e]);
    atomicAdd(&g_cnt[d], 1);
}

__global__ void k_dinv(int N) {
    int i = blockIdx.x * blockDim.x + threadIdx.x;
    if (i >= N) return;
    float dg = g_deg[i];
    g_dinv[i] = (dg > 0.0f) ? rsqrtf(dg) : 0.0f;
}

// --- 2-level exclusive scan ---
__global__ void k_scan1(int N) {
    __shared__ int sh[256];
    int t = threadIdx.x;
    int i = blockIdx.x * 256 + t;
    int v = (i < N) ? g_cnt[i] : 0;
    sh[t] = v;
    __syncthreads();
#pragma unroll
    for (int off = 1; off < 256; off <<= 1) {
        int a = (t >= off) ? sh[t - off] : 0;
        __syncthreads();
        sh[t] += a;
        __syncthreads();
    }
    if (i < N) g_off[i] = sh[t] - v;
    if (t == 255) g_bsum[blockIdx.x] = sh[255];
}

__global__ void k_scan2(int NB) {
    __shared__ int sh[NB_MAX];
    int t = threadIdx.x;
    int v = (t < NB) ? g_bsum[t] : 0;
    sh[t] = v;
    __syncthreads();
#pragma unroll
    for (int off = 1; off < NB_MAX; off <<= 1) {
        int a = (t >= off) ? sh[t - off] : 0;
        __syncthreads();
        sh[t] += a;
        __syncthreads();
    }
    if (t < NB) g_bscan[t] = sh[t] - v;
}

__global__ void k_scan3(int N) {
    int i = blockIdx.x * blockDim.x + threadIdx.x;
    if (i >= N) return;
    int rp = g_off[i] + g_bscan[i >> 8];
    g_rowptr[i] = rp;
    g_cursor[i] = rp;
}

__global__ void k_fill(const void* __restrict__ ei, const float* __restrict__ w, int E) {
    int e = blockIdx.x * blockDim.x + threadIdx.x;
    if (e >= E) return;
    int s, d;
    edge_decode(ei, E, e, s, d);
    int pos = atomicAdd(&g_cursor[d], 1);
    g_csrc[pos] = s;
    g_cnorm[pos] = g_dinv[s] * w[e] * g_dinv[d];
}

// ---------------------------------------------------------------------------
// tf32 tensor-core GEMM: C[M,128] = act(X[M,K]) @ W[K,128]
// BM=128, BN=128, BK=32; 256 threads (8 warps, 2 in M x 4 in N).
// Warp tile 64x32 = 4x4 mma tiles of m16n8k8. ldmatrix-fed, XOR-swizzled smem.
// ---------------------------------------------------------------------------
#define SMSTRIDE 40   // floats per smem row (160 B, 16B-aligned, swizzle-friendly)

__device__ __forceinline__ unsigned f2tf(float f) {
    unsigned r;
    asm("cvt.rna.tf32.f32 %0, %1;" : "=r"(r) : "f"(f));
    return r;
}
__device__ __forceinline__ void ldsm4(unsigned& r0, unsigned& r1,
                                      unsigned& r2, unsigned& r3, unsigned a) {
    asm volatile("ldmatrix.sync.aligned.m8n8.x4.shared.b16 {%0,%1,%2,%3}, [%4];"
                 : "=r"(r0), "=r"(r1), "=r"(r2), "=r"(r3) : "r"(a));
}
__device__ __forceinline__ void ldsm2(unsigned& r0, unsigned& r1, unsigned a) {
    asm volatile("ldmatrix.sync.aligned.m8n8.x2.shared.b16 {%0,%1}, [%2];"
                 : "=r"(r0), "=r"(r1) : "r"(a));
}
__device__ __forceinline__ void mma_tf32(float* c, const unsigned* a, const unsigned* b) {
    asm volatile(
        "mma.sync.aligned.m16n8k8.row.col.f32.tf32.tf32.f32 "
        "{%0,%1,%2,%3}, {%4,%5,%6,%7}, {%8,%9}, {%0,%1,%2,%3};"
        : "+f"(c[0]), "+f"(c[1]), "+f"(c[2]), "+f"(c[3])
        : "r"(a[0]), "r"(a[1]), "r"(a[2]), "r"(a[3]), "r"(b[0]), "r"(b[1]));
}

template <bool RELU>
__global__ __launch_bounds__(256) void k_tgemm(
    const float* __restrict__ X, const float* __restrict__ W,
    float* __restrict__ C, int M, int K)
{
    __shared__ __align__(128) unsigned As[128 * SMSTRIDE];   // X tile, tf32 bits
    __shared__ __align__(128) unsigned Bs[128 * SMSTRIDE];   // W tile transposed [n][k]

    const int tid = threadIdx.x;
    const int lane = tid & 31;
    const int wid = tid >> 5;
    const int warp_m = wid & 1;        // 0..1 -> 64 rows each
    const int warp_n = wid >> 1;       // 0..3 -> 32 cols each
    const int rowBase = blockIdx.x * 128;

    const unsigned sA = (unsigned)__cvta_generic_to_shared(As);
    const unsigned sB = (unsigned)__cvta_generic_to_shared(Bs);

    // ldmatrix per-thread addressing
    const int aRowL = ((lane >> 3) & 1) * 8 + (lane & 7);  // row within 16-row tile
    const int aColS = (lane >> 4) * 16;                    // 16B chunk select
    const unsigned swzA = ((unsigned)(aRowL & 4)) << 2;
    const int bRowL = lane & 7;
    const int bColS = ((lane >> 3) & 1) * 16;
    const unsigned swzB = ((unsigned)(bRowL & 4)) << 2;

    unsigned aBase[4], bBase[4];
#pragma unroll
    for (int mt = 0; mt < 4; mt++)
        aBase[mt] = sA + ((warp_m * 64 + mt * 16 + aRowL) * SMSTRIDE) * 4 + aColS;
#pragma unroll
    for (int nt = 0; nt < 4; nt++)
        bBase[nt] = sB + ((warp_n * 32 + nt * 8 + bRowL) * SMSTRIDE) * 4 + bColS;

    float acc[4][4][4];
#pragma unroll
    for (int i = 0; i < 4; i++)
#pragma unroll
        for (int j = 0; j < 4; j++)
#pragma unroll
            for (int v = 0; v < 4; v++) acc[i][j][v] = 0.0f;

    for (int k0 = 0; k0 < K; k0 += 32) {
        // --- load X tile 128x32 (tf32), swizzled ---
#pragma unroll
        for (int it = 0; it < 4; it++) {
            int idx = it * 256 + tid;          // 1024 float4 slots
            int row = idx >> 3;
            int c4 = idx & 7;
            float4 xv = make_float4(0.f, 0.f, 0.f, 0.f);
            int gr = rowBase + row;
            if (gr < M) xv = *(const float4*)(X + (size_t)gr * K + k0 + c4 * 4);
            if (RELU) {
                xv.x = fmaxf(xv.x, 0.f); xv.y = fmaxf(xv.y, 0.f);
                xv.z = fmaxf(xv.z, 0.f); xv.w = fmaxf(xv.w, 0.f);
            }
            uint4 tv = make_uint4(f2tf(xv.x), f2tf(xv.y), f2tf(xv.z), f2tf(xv.w));
            unsigned boff = row * SMSTRIDE * 4 + ((c4 * 16) ^ (((unsigned)(row & 4)) << 2));
            *(uint4*)((char*)As + boff) = tv;
        }
        // --- load W tile 32x128, store transposed [n][k], swizzled ---
#pragma unroll
        for (int it = 0; it < 4; it++) {
            int idx = it * 256 + tid;          // 1024 float4 slots
            int kr = idx >> 5;                 // 0..31
            int n4 = idx & 31;                 // 0..31 (float4 along n)
            float4 wv = *(const float4*)(W + (size_t)(k0 + kr) * 128 + n4 * 4);
            unsigned t0 = f2tf(wv.x), t1 = f2tf(wv.y), t2 = f2tf(wv.z), t3 = f2tf(wv.w);
            int r0 = n4 * 4;
#pragma unroll
            for (int j = 0; j < 4; j++) {
                unsigned tj = (j == 0) ? t0 : (j == 1) ? t1 : (j == 2) ? t2 : t3;
                int row = r0 + j;
                unsigned boff = row * SMSTRIDE * 4 + ((kr * 4) ^ (((unsigned)(row & 4)) << 2));
                *(unsigned*)((char*)Bs + boff) = tj;
            }
        }
        __syncthreads();

#pragma unroll
        for (int ks = 0; ks < 4; ks++) {
            unsigned afrag[4][4], bfrag[4][2];
#pragma unroll
            for (int mt = 0; mt < 4; mt++)
                ldsm4(afrag[mt][0], afrag[mt][1], afrag[mt][2], afrag[mt][3],
                      (aBase[mt] + ks * 32) ^ swzA);
#pragma unroll
            for (int nt = 0; nt < 4; nt++)
                ldsm2(bfrag[nt][0], bfrag[nt][1], (bBase[nt] + ks * 32) ^ swzB);
#pragma unroll
            for (int mt = 0; mt < 4; mt++)
#pragma unroll
                for (int nt = 0; nt < 4; nt++)
                    mma_tf32(acc[mt][nt], afrag[mt], bfrag[nt]);
        }
        __syncthreads();
    }

    // --- epilogue ---
    const int crow = lane >> 2;
    const int ccol = (lane & 3) * 2;
#pragma unroll
    for (int mt = 0; mt < 4; mt++) {
        int r0 = rowBase + warp_m * 64 + mt * 16 + crow;
#pragma unroll
        for (int nt = 0; nt < 4; nt++) {
            int col = warp_n * 32 + nt * 8 + ccol;
            if (r0 < M) {
                float2 v = make_float2(acc[mt][nt][0], acc[mt][nt][1]);
                *(float2*)(C + (size_t)r0 * 128 + col) = v;
            }
            if (r0 + 8 < M) {
                float2 v = make_float2(acc[mt][nt][2], acc[mt][nt][3]);
                *(float2*)(C + (size_t)(r0 + 8) * 128 + col) = v;
            }
        }
    }
}

// ---------------------------------------------------------------------------
// CSR gather: one warp per dst node.
// ---------------------------------------------------------------------------
__global__ __launch_bounds__(256) void k_gather(
    const float* __restrict__ lin, const float* __restrict__ bias,
    float* __restrict__ out, int N)
{
    int warp = (blockIdx.x * blockDim.x + threadIdx.x) >> 5;
    if (warp >= N) return;
    int lane = threadIdx.x & 31;
    int d = warp;

    float di = g_dinv[d];
    float s = di * di;
    float4 b4 = ((const float4*)bias)[lane];
    float4 v = ((const float4*)lin)[(size_t)d * 32 + lane];
    float4 acc = make_float4(fmaf(v.x, s, b4.x), fmaf(v.y, s, b4.y),
                             fmaf(v.z, s, b4.z), fmaf(v.w, s, b4.w));

    int beg = g_rowptr[d];
    int end = beg + g_cnt[d];
    int e = beg;
    for (; e + 1 < end; e += 2) {
        int s0 = g_csrc[e];     float n0 = g_cnorm[e];
        int s1 = g_csrc[e + 1]; float n1 = g_cnorm[e + 1];
        float4 u0 = ((const float4*)lin)[(size_t)s0 * 32 + lane];
        float4 u1 = ((const float4*)lin)[(size_t)s1 * 32 + lane];
        acc.x = fmaf(u0.x, n0, acc.x); acc.y = fmaf(u0.y, n0, acc.y);
        acc.z = fmaf(u0.z, n0, acc.z); acc.w = fmaf(u0.w, n0, acc.w);
        acc.x = fmaf(u1.x, n1, acc.x); acc.y = fmaf(u1.y, n1, acc.y);
        acc.z = fmaf(u1.z, n1, acc.z); acc.w = fmaf(u1.w, n1, acc.w);
    }
    if (e < end) {
        int s0 = g_csrc[e]; float n0 = g_cnorm[e];
        float4 u0 = ((const float4*)lin)[(size_t)s0 * 32 + lane];
        acc.x = fmaf(u0.x, n0, acc.x); acc.y = fmaf(u0.y, n0, acc.y);
        acc.z = fmaf(u0.z, n0, acc.z); acc.w = fmaf(u0.w, n0, acc.w);
    }
    ((float4*)out)[(size_t)d * 32 + lane] = acc;
}

// ---------------------------------------------------------------------------

static inline int cdiv(long long a, long long b) { return (int)((a + b - 1) / b); }

extern "C" void kernel_launch(void* const* d_in, const int* in_sizes, int n_in,
                              void* d_out, int out_size)
{
    const float* x   = (const float*)d_in[0];
    const void*  ei  = d_in[1];
    const float* ew  = (const float*)d_in[2];
    const float* W1  = (const float*)d_in[3];
    const float* b1  = (const float*)d_in[4];
    const float* W2  = (const float*)d_in[5];
    const float* b2  = (const float*)d_in[6];
    float* out = (float*)d_out;

    const int HID = in_sizes[4];                 // 128
    const int K1  = in_sizes[3] / HID;           // 256
    const int N   = in_sizes[0] / K1;            // 100000
    const int E   = in_sizes[2];                 // 1600000

    float* A; float* B;
    cudaGetSymbolAddress((void**)&A, g_A);
    cudaGetSymbolAddress((void**)&B, g_B);

    const int T = 256;
    const int NB = cdiv(N, 256);

    // --- graph normalization + CSR build ---
    k_detect<<<1, T>>>((const unsigned*)ei);
    k_initdeg<<<cdiv(N, T), T>>>(N);
    k_deg<<<cdiv(E, T), T>>>(ei, ew, E);
    k_dinv<<<cdiv(N, T), T>>>(N);
    k_scan1<<<NB, 256>>>(N);
    k_scan2<<<1, NB_MAX>>>(NB);
    k_scan3<<<cdiv(N, T), T>>>(N);
    k_fill<<<cdiv(E, T), T>>>(ei, ew, E);

    // --- layer 1 ---
    k_tgemm<false><<<cdiv(N, 128), T>>>(x, W1, A, N, K1);
    k_gather<<<cdiv((long long)N * 32, T), T>>>(A, b1, B, N);

    // --- layer 2 ---
    k_tgemm<true><<<cdiv(N, 128), T>>>(B, W2, A, N, HID);
    k_gather<<<cdiv((long long)N * 32, T), T>>>(A, b2, out, N);
}